// round 1
// baseline (speedup 1.0000x reference)
#include <cuda_runtime.h>
#include <cuda_bf16.h>

// Problem constants
#define BATCH   4
#define NSEQ    4096
#define DMODEL  1024
#define NH      16
#define DK      64
#define DV      64
#define MROWS   (BATCH * NSEQ)      // 16384
#define BH      (BATCH * NH)        // 64
#define KV_CHUNKS 8

// Scratch (device globals: allocation-free rule)
__device__ float g_q[MROWS * DMODEL];
__device__ float g_k[MROWS * DMODEL];
__device__ float g_v[MROWS * DMODEL];
__device__ float g_kvpart[KV_CHUNKS * BH * DK * DV];
__device__ float g_kvn[BH * DK * DV];
__device__ float g_mid[MROWS * DMODEL];

// ---------------------------------------------------------------------------
// SGEMM NT: C[M,N] = A[M,K] * B[N,K]^T + bias[N]
// A row-major [M,K], B row-major [N,K] (so both K-contiguous).
// 128x128 block tile, BK=16, 256 threads, 8x8 per thread, double buffered.
// ---------------------------------------------------------------------------
#define BM 128
#define BN 128
#define BK 16
#define PAD 4

__global__ __launch_bounds__(256, 2)
void sgemm_nt_bias(const float* __restrict__ A, const float* __restrict__ B,
                   const float* __restrict__ bias, float* __restrict__ C,
                   int M, int N, int K)
{
    __shared__ float As[2][BK][BM + PAD];
    __shared__ float Bs[2][BK][BN + PAD];

    const int tid = threadIdx.x;
    const int bm = blockIdx.y * BM;
    const int bn = blockIdx.x * BN;
    const int tx = tid & 15;        // col group (0..15)
    const int ty = tid >> 4;        // row group (0..15)

    const float* Ablk = A + (size_t)bm * K;
    const float* Bblk = B + (size_t)bn * K;

    float acc[8][8];
#pragma unroll
    for (int i = 0; i < 8; i++)
#pragma unroll
        for (int j = 0; j < 8; j++) acc[i][j] = 0.f;

    // loader lambda: tile at k-offset kt into buffer buf
    auto load_tile = [&](int kt, int buf) {
#pragma unroll
        for (int i = 0; i < 2; i++) {
            int idx = tid + i * 256;     // 0..511 float4 slots
            int row = idx >> 2;          // 0..127
            int kq  = (idx & 3) * 4;     // 0,4,8,12
            float4 av = *(const float4*)(Ablk + (size_t)row * K + kt + kq);
            As[buf][kq + 0][row] = av.x;
            As[buf][kq + 1][row] = av.y;
            As[buf][kq + 2][row] = av.z;
            As[buf][kq + 3][row] = av.w;
            float4 bv = *(const float4*)(Bblk + (size_t)row * K + kt + kq);
            Bs[buf][kq + 0][row] = bv.x;
            Bs[buf][kq + 1][row] = bv.y;
            Bs[buf][kq + 2][row] = bv.z;
            Bs[buf][kq + 3][row] = bv.w;
        }
    };

    const int nk = K / BK;
    load_tile(0, 0);
    __syncthreads();

    for (int kt = 0; kt < nk; kt++) {
        int buf = kt & 1;
        if (kt + 1 < nk) load_tile((kt + 1) * BK, buf ^ 1);
#pragma unroll
        for (int kk = 0; kk < BK; kk++) {
            float4 a0 = *(const float4*)&As[buf][kk][ty * 8];
            float4 a1 = *(const float4*)&As[buf][kk][ty * 8 + 4];
            float4 b0 = *(const float4*)&Bs[buf][kk][tx * 8];
            float4 b1 = *(const float4*)&Bs[buf][kk][tx * 8 + 4];
            float a[8] = {a0.x, a0.y, a0.z, a0.w, a1.x, a1.y, a1.z, a1.w};
            float b[8] = {b0.x, b0.y, b0.z, b0.w, b1.x, b1.y, b1.z, b1.w};
#pragma unroll
            for (int i = 0; i < 8; i++)
#pragma unroll
                for (int j = 0; j < 8; j++)
                    acc[i][j] = fmaf(a[i], b[j], acc[i][j]);
        }
        __syncthreads();
    }

    // epilogue
#pragma unroll
    for (int i = 0; i < 8; i++) {
        int row = bm + ty * 8 + i;
#pragma unroll
        for (int j = 0; j < 8; j += 4) {
            int col = bn + tx * 8 + j;
            float4 o;
            o.x = acc[i][j + 0] + bias[col + 0];
            o.y = acc[i][j + 1] + bias[col + 1];
            o.z = acc[i][j + 2] + bias[col + 2];
            o.w = acc[i][j + 3] + bias[col + 3];
            *(float4*)(C + (size_t)row * N + col) = o;
        }
    }
}

// ---------------------------------------------------------------------------
// kv partial: part[chunk][bh][k][v] = sum over n in chunk of K[b,n,h,k]*V[b,n,h,v]
// grid (BH, KV_CHUNKS), 256 threads; thread owns 4x4 of the 64x64 output.
// ---------------------------------------------------------------------------
__global__ __launch_bounds__(256)
void kv_partial_kernel(const float* __restrict__ Kp, const float* __restrict__ Vp,
                       float* __restrict__ part)
{
    const int bh = blockIdx.x;
    const int b = bh / NH, h = bh % NH;
    const int chunk = blockIdx.y;
    const int NPER = NSEQ / KV_CHUNKS;   // 512
    const int n0 = chunk * NPER;

    __shared__ float Ks[16][64];
    __shared__ float Vs[16][64];

    const int tid = threadIdx.x;
    const int tk = (tid >> 4) * 4;   // k base 0..60
    const int tv = (tid & 15) * 4;   // v base 0..60

    float acc[4][4];
#pragma unroll
    for (int i = 0; i < 4; i++)
#pragma unroll
        for (int j = 0; j < 4; j++) acc[i][j] = 0.f;

    const int lr = tid >> 4;          // load row 0..15
    const int lc = (tid & 15) * 4;    // load col

    for (int n = n0; n < n0 + NPER; n += 16) {
        size_t base = ((size_t)(b * NSEQ + n + lr)) * DMODEL + h * DK + lc;
        *(float4*)&Ks[lr][lc] = *(const float4*)(Kp + base);
        *(float4*)&Vs[lr][lc] = *(const float4*)(Vp + base);
        __syncthreads();
#pragma unroll
        for (int rr = 0; rr < 16; rr++) {
            float kr[4], vr[4];
#pragma unroll
            for (int i = 0; i < 4; i++) kr[i] = Ks[rr][tk + i];
#pragma unroll
            for (int j = 0; j < 4; j++) vr[j] = Vs[rr][tv + j];
#pragma unroll
            for (int i = 0; i < 4; i++)
#pragma unroll
                for (int j = 0; j < 4; j++)
                    acc[i][j] = fmaf(kr[i], vr[j], acc[i][j]);
        }
        __syncthreads();
    }

    float* out = part + ((size_t)chunk * BH + bh) * (DK * DV);
#pragma unroll
    for (int i = 0; i < 4; i++)
#pragma unroll
        for (int j = 0; j < 4; j++)
            out[(tk + i) * DV + tv + j] = acc[i][j];
}

// ---------------------------------------------------------------------------
// Reduce the KV_CHUNKS partials (fixed order => deterministic) and apply xnorm:
// kvn[bh,k,:] = kv[bh,k,:] * gamma[h] / ||kv[bh,k,:]||_2
// One warp per (bh,k) row (4096 rows). Each lane handles v=lane, v=lane+32.
// ---------------------------------------------------------------------------
__global__ __launch_bounds__(256)
void kv_reduce_norm_kernel(const float* __restrict__ part,
                           const float* __restrict__ gamma,
                           float* __restrict__ kvn)
{
    const int row = blockIdx.x * 8 + (threadIdx.x >> 5);  // 0..4095
    const int lane = threadIdx.x & 31;
    const int bh = row >> 6;         // 0..63
    const int k  = row & 63;
    const int h  = bh % NH;

    float s0 = 0.f, s1 = 0.f;
#pragma unroll
    for (int c = 0; c < KV_CHUNKS; c++) {
        const float* p = part + ((size_t)c * BH + bh) * (DK * DV) + k * DV;
        s0 += p[lane];
        s1 += p[lane + 32];
    }
    float ss = s0 * s0 + s1 * s1;
#pragma unroll
    for (int off = 16; off > 0; off >>= 1)
        ss += __shfl_xor_sync(0xffffffffu, ss, off);
    float scale = gamma[h] * rsqrtf(ss);

    float* o = kvn + (size_t)bh * (DK * DV) + k * DV;
    o[lane]      = s0 * scale;
    o[lane + 32] = s1 * scale;
}

// ---------------------------------------------------------------------------
// mid[b,n,h,:] = (q[b,n,h,:] * gamma[h] / ||q[b,n,h,:]||) @ kvn[bh]  (64x64)
// grid (BH, NSEQ/64), block 256 = 4 groups of 64 threads; group handles one n.
// ---------------------------------------------------------------------------
__global__ __launch_bounds__(256)
void apply_kernel(const float* __restrict__ Qp, const float* __restrict__ kvn,
                  const float* __restrict__ gamma, float* __restrict__ mid)
{
    const int bh = blockIdx.x;
    const int b = bh / NH, h = bh % NH;

    __shared__ float Ks[64][65];
    __shared__ float qs[4][64];

    const int tid = threadIdx.x;
    // load kvn tile (4096 floats)
    for (int i = tid; i < DK * DV; i += 256)
        Ks[i >> 6][i & 63] = kvn[(size_t)bh * (DK * DV) + i];
    __syncthreads();

    const int g = tid >> 6;      // group 0..3
    const int t = tid & 63;      // v index
    const float gh = gamma[h];
    const int n_base = blockIdx.y * 64;

    for (int it = 0; it < 16; it++) {
        int n = n_base + it * 4 + g;
        size_t qoff = ((size_t)(b * NSEQ + n)) * DMODEL + h * DK;
        qs[g][t] = Qp[qoff + t];
        __syncthreads();
        float acc = 0.f, qq = 0.f;
#pragma unroll
        for (int k = 0; k < DK; k++) {
            float qv = qs[g][k];
            qq  = fmaf(qv, qv, qq);
            acc = fmaf(qv, Ks[k][t], acc);
        }
        mid[qoff + t] = acc * gh * rsqrtf(qq);
        __syncthreads();
    }
}

// ---------------------------------------------------------------------------
extern "C" void kernel_launch(void* const* d_in, const int* in_sizes, int n_in,
                              void* d_out, int out_size)
{
    const float* queries = (const float*)d_in[0];
    const float* keys    = (const float*)d_in[1];
    const float* values  = (const float*)d_in[2];
    const float* Wq = (const float*)d_in[3];
    const float* bq = (const float*)d_in[4];
    const float* Wk = (const float*)d_in[5];
    const float* bk = (const float*)d_in[6];
    const float* Wv = (const float*)d_in[7];
    const float* bv = (const float*)d_in[8];
    const float* Wo = (const float*)d_in[9];
    const float* bo = (const float*)d_in[10];
    const float* gamma = (const float*)d_in[11];
    float* out = (float*)d_out;

    float *q, *k, *v, *kvpart, *kvn, *mid;
    cudaGetSymbolAddress((void**)&q,      g_q);
    cudaGetSymbolAddress((void**)&k,      g_k);
    cudaGetSymbolAddress((void**)&v,      g_v);
    cudaGetSymbolAddress((void**)&kvpart, g_kvpart);
    cudaGetSymbolAddress((void**)&kvn,    g_kvn);
    cudaGetSymbolAddress((void**)&mid,    g_mid);

    dim3 gemm_grid(DMODEL / BN, MROWS / BM);   // (8, 128)
    dim3 gemm_blk(256);

    // Projections
    sgemm_nt_bias<<<gemm_grid, gemm_blk>>>(queries, Wq, bq, q, MROWS, DMODEL, DMODEL);
    sgemm_nt_bias<<<gemm_grid, gemm_blk>>>(keys,    Wk, bk, k, MROWS, DMODEL, DMODEL);
    sgemm_nt_bias<<<gemm_grid, gemm_blk>>>(values,  Wv, bv, v, MROWS, DMODEL, DMODEL);

    // kv = K^T V per head (chunked partials, fixed-order reduce => deterministic)
    kv_partial_kernel<<<dim3(BH, KV_CHUNKS), 256>>>(k, v, kvpart);
    kv_reduce_norm_kernel<<<dim3(BH * DK / 8), 256>>>(kvpart, gamma, kvn);

    // mid = xnorm(q) @ kvn
    apply_kernel<<<dim3(BH, NSEQ / 64), 256>>>(q, kvn, gamma, mid);

    // final projection
    sgemm_nt_bias<<<gemm_grid, gemm_blk>>>(mid, Wo, bo, out, MROWS, DMODEL, DMODEL);
}

// round 5
// speedup vs baseline: 2.4952x; 2.4952x over previous
#include <cuda_runtime.h>
#include <cuda_bf16.h>
#include <cstdint>

// Problem constants
#define BATCH   4
#define NSEQ    4096
#define DMODEL  1024
#define NH      16
#define DK      64
#define DV      64
#define MROWS   (BATCH * NSEQ)      // 16384
#define BH      (BATCH * NH)        // 64
#define KV_CHUNKS 8

// Scratch (device globals: allocation-free rule)
__device__ float g_q[MROWS * DMODEL];
__device__ float g_k[MROWS * DMODEL];
__device__ float g_v[MROWS * DMODEL];
__device__ float g_kvpart[KV_CHUNKS * BH * DK * DV];
__device__ float g_kvn[BH * DK * DV];
__device__ float g_mid[MROWS * DMODEL];
__device__ __nv_bfloat16 g_ah[MROWS * DMODEL];   // activation hi
__device__ __nv_bfloat16 g_al[MROWS * DMODEL];   // activation lo
__device__ __nv_bfloat16 g_wh[DMODEL * DMODEL];  // weight hi
__device__ __nv_bfloat16 g_wl[DMODEL * DMODEL];  // weight lo

// ---------------------------------------------------------------------------
// helpers (baseline ISA only: cp.async, ldmatrix, mma.sync — all sm_80+)
// ---------------------------------------------------------------------------
__device__ __forceinline__ uint32_t smem_u32(const void* p) {
    uint32_t a;
    asm("{ .reg .u64 t; cvta.to.shared.u64 t, %1; cvt.u32.u64 %0, t; }"
        : "=r"(a) : "l"(p));
    return a;
}
__device__ __forceinline__ void cp16(uint32_t s, const void* g) {
    asm volatile("cp.async.cg.shared.global [%0], [%1], 16;" :: "r"(s), "l"(g));
}
__device__ __forceinline__ void cp_commit() {
    asm volatile("cp.async.commit_group;" ::: "memory");
}
__device__ __forceinline__ void cp_wait_allbut2() {
    asm volatile("cp.async.wait_group 2;" ::: "memory");
}
__device__ __forceinline__ uint32_t swz128(uint32_t off) {
    return off ^ ((off >> 3) & 0x70);
}
__device__ __forceinline__ void ldsm_x4(uint32_t (&r)[4], uint32_t addr) {
    asm volatile("ldmatrix.sync.aligned.m8n8.x4.shared.b16 {%0,%1,%2,%3}, [%4];"
                 : "=r"(r[0]), "=r"(r[1]), "=r"(r[2]), "=r"(r[3]) : "r"(addr));
}
__device__ __forceinline__ void mma16816(float* c, const uint32_t* a, const uint32_t* b) {
    asm volatile("mma.sync.aligned.m16n8k16.row.col.f32.bf16.bf16.f32 "
                 "{%0,%1,%2,%3}, {%4,%5,%6,%7}, {%8,%9}, {%0,%1,%2,%3};"
                 : "+f"(c[0]), "+f"(c[1]), "+f"(c[2]), "+f"(c[3])
                 : "r"(a[0]), "r"(a[1]), "r"(a[2]), "r"(a[3]), "r"(b[0]), "r"(b[1]));
}

// ---------------------------------------------------------------------------
// fp32 -> bf16 hi/lo split (vectorized by 4)
// ---------------------------------------------------------------------------
__global__ __launch_bounds__(256)
void split_kernel(const float4* __restrict__ x, __nv_bfloat16* __restrict__ hi,
                  __nv_bfloat16* __restrict__ lo, int n4)
{
    int i = blockIdx.x * 256 + threadIdx.x;
    if (i >= n4) return;
    float4 v = x[i];
    __nv_bfloat16 h0 = __float2bfloat16(v.x), h1 = __float2bfloat16(v.y);
    __nv_bfloat16 h2 = __float2bfloat16(v.z), h3 = __float2bfloat16(v.w);
    __nv_bfloat16 l0 = __float2bfloat16(v.x - __bfloat162float(h0));
    __nv_bfloat16 l1 = __float2bfloat16(v.y - __bfloat162float(h1));
    __nv_bfloat16 l2 = __float2bfloat16(v.z - __bfloat162float(h2));
    __nv_bfloat16 l3 = __float2bfloat16(v.w - __bfloat162float(h3));
    size_t o = (size_t)i * 4;
    *(__nv_bfloat162*)(hi + o)     = __halves2bfloat162(h0, h1);
    *(__nv_bfloat162*)(hi + o + 2) = __halves2bfloat162(h2, h3);
    *(__nv_bfloat162*)(lo + o)     = __halves2bfloat162(l0, l1);
    *(__nv_bfloat162*)(lo + o + 2) = __halves2bfloat162(l2, l3);
}

// ---------------------------------------------------------------------------
// HMMA bf16x3 GEMM: C[M,1024] = A[M,1024] x B[1024,1024]^T + bias
// CTA tile 128x128, BK=64, 3-stage cp.async pipeline, 8 warps (4M x 2N),
// warp tile 32x64, mma.sync m16n8k16, fp32 register accumulators.
// ---------------------------------------------------------------------------
#define GM 128
#define GN 128
#define GK 64
#define NSTAGE 3
#define TILE_B   16384                 // 128 rows x 128 bytes (64 bf16)
#define STAGE_B  (4 * TILE_B)          // Ahi,Alo,Bhi,Blo = 64KB
#define KITERS   (DMODEL / GK)         // 16
#define DSMEM_SZ (NSTAGE * STAGE_B + 1024)

__device__ __forceinline__ void load_stage(uint32_t base, int s, int tid,
    const __nv_bfloat16* __restrict__ Ah, const __nv_bfloat16* __restrict__ Al,
    const __nv_bfloat16* __restrict__ Bh, const __nv_bfloat16* __restrict__ Bl,
    int bm, int bn)
{
    uint32_t sb = base + (s % NSTAGE) * STAGE_B;
    const __nv_bfloat16* srcs[4] = {
        Ah + (size_t)bm * DMODEL + s * GK,
        Al + (size_t)bm * DMODEL + s * GK,
        Bh + (size_t)bn * DMODEL + s * GK,
        Bl + (size_t)bn * DMODEL + s * GK };
#pragma unroll
    for (int t = 0; t < 4; t++) {
        const __nv_bfloat16* P = srcs[t];
        uint32_t tb = sb + t * TILE_B;
#pragma unroll
        for (int i = 0; i < 4; i++) {
            int chunk = tid + i * 256;       // 0..1023
            int r = chunk >> 3;              // row 0..127
            int c = chunk & 7;               // 16B chunk 0..7
            cp16(tb + swz128(r * 128 + c * 16), P + (size_t)r * DMODEL + c * 8);
        }
    }
}

__global__ __launch_bounds__(256, 1)
void gemm_bf16x3(const __nv_bfloat16* __restrict__ Ah, const __nv_bfloat16* __restrict__ Al,
                 const __nv_bfloat16* __restrict__ Bh, const __nv_bfloat16* __restrict__ Bl,
                 const float* __restrict__ bias, float* __restrict__ C)
{
    extern __shared__ char dsm[];
    const int tid = threadIdx.x;
    const int wid = tid >> 5;
    const int lane = tid & 31;
    const int wm = wid & 3;          // warp row 0..3  (32 rows each)
    const int wn = wid >> 2;         // warp col 0..1  (64 cols each)
    const int bm = blockIdx.y * GM;
    const int bn = blockIdx.x * GN;

    uint32_t base = (smem_u32(dsm) + 1023) & ~1023u;

    // ldmatrix lane address components
    const int a_r  = (lane & 15);            // A: row within m16 tile
    const int a_kh = ((lane >> 4) & 1) * 16; // A: 16B k-half select
    const int b_g  = lane >> 3;              // B: quad group 0..3
    const int b_r  = (lane & 7) + ((b_g >> 1) << 3); // B: row within n16 pair
    const int b_kh = (b_g & 1) * 16;         // B: 16B k-half select

    float acc[2][8][4];
#pragma unroll
    for (int mt = 0; mt < 2; mt++)
#pragma unroll
        for (int nt = 0; nt < 8; nt++)
#pragma unroll
            for (int j = 0; j < 4; j++) acc[mt][nt][j] = 0.f;

    // prologue: fill all 3 stages
    load_stage(base, 0, tid, Ah, Al, Bh, Bl, bm, bn); cp_commit();
    load_stage(base, 1, tid, Ah, Al, Bh, Bl, bm, bn); cp_commit();
    load_stage(base, 2, tid, Ah, Al, Bh, Bl, bm, bn); cp_commit();

    for (int s = 0; s < KITERS; s++) {
        cp_wait_allbut2();               // stage s resident
        __syncthreads();
        uint32_t sb  = base + (s % NSTAGE) * STAGE_B;
        uint32_t Ahb = sb, Alb = sb + TILE_B, Bhb = sb + 2 * TILE_B, Blb = sb + 3 * TILE_B;

#pragma unroll
        for (int ks = 0; ks < 4; ks++) {     // 4 x k16 per stage
            const int kb = ks * 32;          // byte offset of k16 chunk
            uint32_t ah[2][4], am[2][4];
#pragma unroll
            for (int mt = 0; mt < 2; mt++) {
                uint32_t off = swz128((wm * 32 + mt * 16 + a_r) * 128 + kb + a_kh);
                ldsm_x4(ah[mt], Ahb + off);
                ldsm_x4(am[mt], Alb + off);
            }
#pragma unroll
            for (int nt = 0; nt < 4; nt++) { // pairs of n8 groups
                uint32_t boff = swz128((wn * 64 + nt * 16 + b_r) * 128 + kb + b_kh);
                uint32_t bh[4], bl[4];
                ldsm_x4(bh, Bhb + boff);
                ldsm_x4(bl, Blb + boff);
#pragma unroll
                for (int mt = 0; mt < 2; mt++) {
                    mma16816(acc[mt][nt * 2],     ah[mt], bh);
                    mma16816(acc[mt][nt * 2],     am[mt], bh);
                    mma16816(acc[mt][nt * 2],     ah[mt], bl);
                    mma16816(acc[mt][nt * 2 + 1], ah[mt], bh + 2);
                    mma16816(acc[mt][nt * 2 + 1], am[mt], bh + 2);
                    mma16816(acc[mt][nt * 2 + 1], ah[mt], bl + 2);
                }
            }
        }
        __syncthreads();
        if (s + NSTAGE < KITERS)
            load_stage(base, s + NSTAGE, tid, Ah, Al, Bh, Bl, bm, bn);
        cp_commit();                     // uniform group count (empty ok)
    }

    // epilogue: c0,c1 -> row g; c2,c3 -> row g+8
    const int g = lane >> 2, t = lane & 3;
#pragma unroll
    for (int mt = 0; mt < 2; mt++) {
        const int row0 = bm + wm * 32 + mt * 16 + g;
#pragma unroll
        for (int nt = 0; nt < 8; nt++) {
            const int col = bn + wn * 64 + nt * 8 + t * 2;
            const float b0 = bias[col], b1 = bias[col + 1];
            float2 o0 = make_float2(acc[mt][nt][0] + b0, acc[mt][nt][1] + b1);
            float2 o1 = make_float2(acc[mt][nt][2] + b0, acc[mt][nt][3] + b1);
            *(float2*)(C + (size_t)row0 * DMODEL + col)       = o0;
            *(float2*)(C + (size_t)(row0 + 8) * DMODEL + col) = o1;
        }
    }
}

// ---------------------------------------------------------------------------
// kv partial: part[chunk][bh][k][v] = sum over n in chunk of K[b,n,h,k]*V[b,n,h,v]
// ---------------------------------------------------------------------------
__global__ __launch_bounds__(256)
void kv_partial_kernel(const float* __restrict__ Kp, const float* __restrict__ Vp,
                       float* __restrict__ part)
{
    const int bh = blockIdx.x;
    const int b = bh / NH, h = bh % NH;
    const int chunk = blockIdx.y;
    const int NPER = NSEQ / KV_CHUNKS;   // 512
    const int n0 = chunk * NPER;

    __shared__ float Ks[16][64];
    __shared__ float Vs[16][64];

    const int tid = threadIdx.x;
    const int tk = (tid >> 4) * 4;
    const int tv = (tid & 15) * 4;

    float acc[4][4];
#pragma unroll
    for (int i = 0; i < 4; i++)
#pragma unroll
        for (int j = 0; j < 4; j++) acc[i][j] = 0.f;

    const int lr = tid >> 4;
    const int lc = (tid & 15) * 4;

    for (int n = n0; n < n0 + NPER; n += 16) {
        size_t basep = ((size_t)(b * NSEQ + n + lr)) * DMODEL + h * DK + lc;
        *(float4*)&Ks[lr][lc] = *(const float4*)(Kp + basep);
        *(float4*)&Vs[lr][lc] = *(const float4*)(Vp + basep);
        __syncthreads();
#pragma unroll
        for (int rr = 0; rr < 16; rr++) {
            float kr[4], vr[4];
#pragma unroll
            for (int i = 0; i < 4; i++) kr[i] = Ks[rr][tk + i];
#pragma unroll
            for (int j = 0; j < 4; j++) vr[j] = Vs[rr][tv + j];
#pragma unroll
            for (int i = 0; i < 4; i++)
#pragma unroll
                for (int j = 0; j < 4; j++)
                    acc[i][j] = fmaf(kr[i], vr[j], acc[i][j]);
        }
        __syncthreads();
    }

    float* out = part + ((size_t)chunk * BH + bh) * (DK * DV);
#pragma unroll
    for (int i = 0; i < 4; i++)
#pragma unroll
        for (int j = 0; j < 4; j++)
            out[(tk + i) * DV + tv + j] = acc[i][j];
}

// ---------------------------------------------------------------------------
__global__ __launch_bounds__(256)
void kv_reduce_norm_kernel(const float* __restrict__ part,
                           const float* __restrict__ gamma,
                           float* __restrict__ kvn)
{
    const int row = blockIdx.x * 8 + (threadIdx.x >> 5);
    const int lane = threadIdx.x & 31;
    const int bh = row >> 6;
    const int k  = row & 63;
    const int h  = bh % NH;

    float s0 = 0.f, s1 = 0.f;
#pragma unroll
    for (int c = 0; c < KV_CHUNKS; c++) {
        const float* p = part + ((size_t)c * BH + bh) * (DK * DV) + k * DV;
        s0 += p[lane];
        s1 += p[lane + 32];
    }
    float ss = s0 * s0 + s1 * s1;
#pragma unroll
    for (int off = 16; off > 0; off >>= 1)
        ss += __shfl_xor_sync(0xffffffffu, ss, off);
    float scale = gamma[h] * rsqrtf(ss);

    float* o = kvn + (size_t)bh * (DK * DV) + k * DV;
    o[lane]      = s0 * scale;
    o[lane + 32] = s1 * scale;
}

// ---------------------------------------------------------------------------
__global__ __launch_bounds__(256)
void apply_kernel(const float* __restrict__ Qp, const float* __restrict__ kvn,
                  const float* __restrict__ gamma, float* __restrict__ mid)
{
    const int bh = blockIdx.x;
    const int b = bh / NH, h = bh % NH;

    __shared__ float Ks[64][65];
    __shared__ float qs[4][64];

    const int tid = threadIdx.x;
    for (int i = tid; i < DK * DV; i += 256)
        Ks[i >> 6][i & 63] = kvn[(size_t)bh * (DK * DV) + i];
    __syncthreads();

    const int g = tid >> 6;
    const int t = tid & 63;
    const float gh = gamma[h];
    const int n_base = blockIdx.y * 64;

    for (int it = 0; it < 16; it++) {
        int n = n_base + it * 4 + g;
        size_t qoff = ((size_t)(b * NSEQ + n)) * DMODEL + h * DK;
        qs[g][t] = Qp[qoff + t];
        __syncthreads();
        float acc = 0.f, qq = 0.f;
#pragma unroll
        for (int k = 0; k < DK; k++) {
            float qv = qs[g][k];
            qq  = fmaf(qv, qv, qq);
            acc = fmaf(qv, Ks[k][t], acc);
        }
        mid[qoff + t] = acc * gh * rsqrtf(qq);
        __syncthreads();
    }
}

// ---------------------------------------------------------------------------
extern "C" void kernel_launch(void* const* d_in, const int* in_sizes, int n_in,
                              void* d_out, int out_size)
{
    const float* queries = (const float*)d_in[0];
    const float* keys    = (const float*)d_in[1];
    const float* values  = (const float*)d_in[2];
    const float* Wq = (const float*)d_in[3];
    const float* bq = (const float*)d_in[4];
    const float* Wk = (const float*)d_in[5];
    const float* bk = (const float*)d_in[6];
    const float* Wv = (const float*)d_in[7];
    const float* bv = (const float*)d_in[8];
    const float* Wo = (const float*)d_in[9];
    const float* bo = (const float*)d_in[10];
    const float* gamma = (const float*)d_in[11];
    float* out = (float*)d_out;

    float *q, *k, *v, *kvpart, *kvn, *mid;
    __nv_bfloat16 *ah, *al, *wh, *wl;
    cudaGetSymbolAddress((void**)&q,      g_q);
    cudaGetSymbolAddress((void**)&k,      g_k);
    cudaGetSymbolAddress((void**)&v,      g_v);
    cudaGetSymbolAddress((void**)&kvpart, g_kvpart);
    cudaGetSymbolAddress((void**)&kvn,    g_kvn);
    cudaGetSymbolAddress((void**)&mid,    g_mid);
    cudaGetSymbolAddress((void**)&ah,     g_ah);
    cudaGetSymbolAddress((void**)&al,     g_al);
    cudaGetSymbolAddress((void**)&wh,     g_wh);
    cudaGetSymbolAddress((void**)&wl,     g_wl);

    cudaFuncSetAttribute(gemm_bf16x3, cudaFuncAttributeMaxDynamicSharedMemorySize, DSMEM_SZ);

    const int ACT_N4 = MROWS * DMODEL / 4;    // 4M float4
    const int W_N4   = DMODEL * DMODEL / 4;   // 256K float4
    dim3 gemm_grid(DMODEL / GN, MROWS / GM);  // (8, 128)

    // Q projection
    split_kernel<<<ACT_N4 / 256, 256>>>((const float4*)queries, ah, al, ACT_N4);
    split_kernel<<<W_N4 / 256, 256>>>((const float4*)Wq, wh, wl, W_N4);
    gemm_bf16x3<<<gemm_grid, 256, DSMEM_SZ>>>(ah, al, wh, wl, bq, q);

    // K projection
    split_kernel<<<ACT_N4 / 256, 256>>>((const float4*)keys, ah, al, ACT_N4);
    split_kernel<<<W_N4 / 256, 256>>>((const float4*)Wk, wh, wl, W_N4);
    gemm_bf16x3<<<gemm_grid, 256, DSMEM_SZ>>>(ah, al, wh, wl, bk, k);

    // V projection
    split_kernel<<<ACT_N4 / 256, 256>>>((const float4*)values, ah, al, ACT_N4);
    split_kernel<<<W_N4 / 256, 256>>>((const float4*)Wv, wh, wl, W_N4);
    gemm_bf16x3<<<gemm_grid, 256, DSMEM_SZ>>>(ah, al, wh, wl, bv, v);

    // kv = K^T V per head; normalize; apply to normalized q
    kv_partial_kernel<<<dim3(BH, KV_CHUNKS), 256>>>(k, v, kvpart);
    kv_reduce_norm_kernel<<<dim3(BH * DK / 8), 256>>>(kvpart, gamma, kvn);
    apply_kernel<<<dim3(BH, NSEQ / 64), 256>>>(q, kvn, gamma, mid);

    // output projection
    split_kernel<<<ACT_N4 / 256, 256>>>((const float4*)mid, ah, al, ACT_N4);
    split_kernel<<<W_N4 / 256, 256>>>((const float4*)Wo, wh, wl, W_N4);
    gemm_bf16x3<<<gemm_grid, 256, DSMEM_SZ>>>(ah, al, wh, wl, bo, out);
}

// round 10
// speedup vs baseline: 3.1652x; 1.2685x over previous
#include <cuda_runtime.h>
#include <cuda_bf16.h>
#include <cuda_fp16.h>
#include <cstdint>

// Problem constants
#define BATCH   4
#define NSEQ    4096
#define DMODEL  1024
#define NH      16
#define DK      64
#define DV      64
#define MROWS   (BATCH * NSEQ)      // 16384
#define BH      (BATCH * NH)        // 64
#define KV_CHUNKS 8

#define WSCALE   256.0f
#define INV_WSCALE (1.0f / 256.0f)

// Scratch (device globals: allocation-free rule)
__device__ float g_q[MROWS * DMODEL];
__device__ float g_k[MROWS * DMODEL];
__device__ float g_v[MROWS * DMODEL];
__device__ float g_kvpart[KV_CHUNKS * BH * DK * DV];
__device__ float g_kvn[BH * DK * DV];
__device__ __half g_ah[MROWS * DMODEL];   // activation hi
__device__ __half g_al[MROWS * DMODEL];   // activation lo
__device__ __half g_wh[DMODEL * DMODEL];  // weight (x256) fp16

// ---------------------------------------------------------------------------
// helpers (baseline ISA only: cp.async, ldmatrix, mma.sync — all sm_80+)
// ---------------------------------------------------------------------------
__device__ __forceinline__ uint32_t smem_u32(const void* p) {
    uint32_t a;
    asm("{ .reg .u64 t; cvta.to.shared.u64 t, %1; cvt.u32.u64 %0, t; }"
        : "=r"(a) : "l"(p));
    return a;
}
__device__ __forceinline__ void cp16(uint32_t s, const void* g) {
    asm volatile("cp.async.cg.shared.global [%0], [%1], 16;" :: "r"(s), "l"(g));
}
__device__ __forceinline__ void cp_commit() {
    asm volatile("cp.async.commit_group;" ::: "memory");
}
__device__ __forceinline__ void cp_wait_allbut2() {
    asm volatile("cp.async.wait_group 2;" ::: "memory");
}
__device__ __forceinline__ uint32_t swz128(uint32_t off) {
    return off ^ ((off >> 3) & 0x70);
}
__device__ __forceinline__ void ldsm_x4(uint32_t (&r)[4], uint32_t addr) {
    asm volatile("ldmatrix.sync.aligned.m8n8.x4.shared.b16 {%0,%1,%2,%3}, [%4];"
                 : "=r"(r[0]), "=r"(r[1]), "=r"(r[2]), "=r"(r[3]) : "r"(addr));
}
__device__ __forceinline__ void mma16816(float* c, const uint32_t* a, const uint32_t* b) {
    asm volatile("mma.sync.aligned.m16n8k16.row.col.f32.f16.f16.f32 "
                 "{%0,%1,%2,%3}, {%4,%5,%6,%7}, {%8,%9}, {%0,%1,%2,%3};"
                 : "+f"(c[0]), "+f"(c[1]), "+f"(c[2]), "+f"(c[3])
                 : "r"(a[0]), "r"(a[1]), "r"(a[2]), "r"(a[3]), "r"(b[0]), "r"(b[1]));
}

// ---------------------------------------------------------------------------
// fp32 -> fp16 hi/lo split for activations (vectorized by 4)
// ---------------------------------------------------------------------------
__global__ __launch_bounds__(256)
void split_act_kernel(const float4* __restrict__ x, __half* __restrict__ hi,
                      __half* __restrict__ lo, int n4)
{
    int i = blockIdx.x * 256 + threadIdx.x;
    if (i >= n4) return;
    float4 v = x[i];
    __half h0 = __float2half(v.x), h1 = __float2half(v.y);
    __half h2 = __float2half(v.z), h3 = __float2half(v.w);
    __half l0 = __float2half(v.x - __half2float(h0));
    __half l1 = __float2half(v.y - __half2float(h1));
    __half l2 = __float2half(v.z - __half2float(h2));
    __half l3 = __float2half(v.w - __half2float(h3));
    size_t o = (size_t)i * 4;
    *(__half2*)(hi + o)     = __halves2half2(h0, h1);
    *(__half2*)(hi + o + 2) = __halves2half2(h2, h3);
    *(__half2*)(lo + o)     = __halves2half2(l0, l1);
    *(__half2*)(lo + o + 2) = __halves2half2(l2, l3);
}

// fp32 -> fp16 weight convert with x256 scale (keeps values in normal range)
__global__ __launch_bounds__(256)
void split_w_kernel(const float4* __restrict__ x, __half* __restrict__ hi, int n4)
{
    int i = blockIdx.x * 256 + threadIdx.x;
    if (i >= n4) return;
    float4 v = x[i];
    size_t o = (size_t)i * 4;
    *(__half2*)(hi + o)     = __halves2half2(__float2half(v.x * WSCALE), __float2half(v.y * WSCALE));
    *(__half2*)(hi + o + 2) = __halves2half2(__float2half(v.z * WSCALE), __float2half(v.w * WSCALE));
}

// ---------------------------------------------------------------------------
// HMMA fp16x2 GEMM: C[M,1024] = A[M,1024] x B[1024,1024]^T * (1/256) + bias
// A as (hi,lo) fp16 pair, B as fp16 (x256). CTA tile 128x128, BK=64,
// 4-buffer / 3-in-flight cp.async pipeline, 8 warps (4M x 2N), warp 32x64.
// ---------------------------------------------------------------------------
#define GM 128
#define GN 128
#define GK 64
#define NSTAGE 4
#define TILE_B   16384                 // 128 rows x 128 bytes (64 fp16)
#define STAGE_B  (3 * TILE_B)          // Ah, Al, Bh = 48KB
#define KITERS   (DMODEL / GK)         // 16
#define DSMEM_SZ (NSTAGE * STAGE_B + 1024)

__device__ __forceinline__ void load_stage(uint32_t base, int s, int tid,
    const __half* __restrict__ Ah, const __half* __restrict__ Al,
    const __half* __restrict__ Bh, int bm, int bn)
{
    uint32_t sb = base + (s % NSTAGE) * STAGE_B;
    const __half* srcs[3] = {
        Ah + (size_t)bm * DMODEL + s * GK,
        Al + (size_t)bm * DMODEL + s * GK,
        Bh + (size_t)bn * DMODEL + s * GK };
#pragma unroll
    for (int t = 0; t < 3; t++) {
        const __half* P = srcs[t];
        uint32_t tb = sb + t * TILE_B;
#pragma unroll
        for (int i = 0; i < 4; i++) {
            int chunk = tid + i * 256;       // 0..1023
            int r = chunk >> 3;              // row 0..127
            int c = chunk & 7;               // 16B chunk 0..7
            cp16(tb + swz128(r * 128 + c * 16), P + (size_t)r * DMODEL + c * 8);
        }
    }
}

__global__ __launch_bounds__(256, 1)
void gemm_fp16x2(const __half* __restrict__ Ah, const __half* __restrict__ Al,
                 const __half* __restrict__ Bh,
                 const float* __restrict__ bias, float* __restrict__ C)
{
    extern __shared__ char dsm[];
    const int tid = threadIdx.x;
    const int wid = tid >> 5;
    const int lane = tid & 31;
    const int wm = wid & 3;          // warp row 0..3  (32 rows each)
    const int wn = wid >> 2;         // warp col 0..1  (64 cols each)
    const int bm = blockIdx.y * GM;
    const int bn = blockIdx.x * GN;

    uint32_t base = (smem_u32(dsm) + 1023) & ~1023u;

    // ldmatrix lane address components
    const int a_r  = (lane & 15);
    const int a_kh = ((lane >> 4) & 1) * 16;
    const int b_g  = lane >> 3;
    const int b_r  = (lane & 7) + ((b_g >> 1) << 3);
    const int b_kh = (b_g & 1) * 16;

    float acc[2][8][4];
#pragma unroll
    for (int mt = 0; mt < 2; mt++)
#pragma unroll
        for (int nt = 0; nt < 8; nt++)
#pragma unroll
            for (int j = 0; j < 4; j++) acc[mt][nt][j] = 0.f;

    // prologue: fill 3 of 4 buffers
    load_stage(base, 0, tid, Ah, Al, Bh, bm, bn); cp_commit();
    load_stage(base, 1, tid, Ah, Al, Bh, bm, bn); cp_commit();
    load_stage(base, 2, tid, Ah, Al, Bh, bm, bn); cp_commit();

    for (int s = 0; s < KITERS; s++) {
        cp_wait_allbut2();               // stage s resident
        __syncthreads();                 // also orders reuse of buffer (s+3)%4

        // issue next load BEFORE compute (targets buffer (s+3)%4 != s%4)
        if (s + 3 < KITERS)
            load_stage(base, s + 3, tid, Ah, Al, Bh, bm, bn);
        cp_commit();                     // uniform group count

        uint32_t sb  = base + (s % NSTAGE) * STAGE_B;
        uint32_t Ahb = sb, Alb = sb + TILE_B, Bhb = sb + 2 * TILE_B;

#pragma unroll
        for (int ks = 0; ks < 4; ks++) {     // 4 x k16 per stage
            const int kb = ks * 32;
            uint32_t ah[2][4], al[2][4];
#pragma unroll
            for (int mt = 0; mt < 2; mt++) {
                uint32_t off = swz128((wm * 32 + mt * 16 + a_r) * 128 + kb + a_kh);
                ldsm_x4(ah[mt], Ahb + off);
                ldsm_x4(al[mt], Alb + off);
            }
#pragma unroll
            for (int nt = 0; nt < 4; nt++) { // pairs of n8 groups
                uint32_t boff = swz128((wn * 64 + nt * 16 + b_r) * 128 + kb + b_kh);
                uint32_t bh[4];
                ldsm_x4(bh, Bhb + boff);
#pragma unroll
                for (int mt = 0; mt < 2; mt++) {
                    mma16816(acc[mt][nt * 2],     ah[mt], bh);
                    mma16816(acc[mt][nt * 2],     al[mt], bh);
                    mma16816(acc[mt][nt * 2 + 1], ah[mt], bh + 2);
                    mma16816(acc[mt][nt * 2 + 1], al[mt], bh + 2);
                }
            }
        }
    }

    // epilogue: c0,c1 -> row g; c2,c3 -> row g+8; scale by 1/256, add bias
    const int g = lane >> 2, t = lane & 3;
#pragma unroll
    for (int mt = 0; mt < 2; mt++) {
        const int row0 = bm + wm * 32 + mt * 16 + g;
#pragma unroll
        for (int nt = 0; nt < 8; nt++) {
            const int col = bn + wn * 64 + nt * 8 + t * 2;
            const float b0 = bias[col], b1 = bias[col + 1];
            float2 o0 = make_float2(fmaf(acc[mt][nt][0], INV_WSCALE, b0),
                                    fmaf(acc[mt][nt][1], INV_WSCALE, b1));
            float2 o1 = make_float2(fmaf(acc[mt][nt][2], INV_WSCALE, b0),
                                    fmaf(acc[mt][nt][3], INV_WSCALE, b1));
            *(float2*)(C + (size_t)row0 * DMODEL + col)       = o0;
            *(float2*)(C + (size_t)(row0 + 8) * DMODEL + col) = o1;
        }
    }
}

// ---------------------------------------------------------------------------
// kv partial: part[chunk][bh][k][v] = sum over n in chunk of K[b,n,h,k]*V[b,n,h,v]
// ---------------------------------------------------------------------------
__global__ __launch_bounds__(256)
void kv_partial_kernel(const float* __restrict__ Kp, const float* __restrict__ Vp,
                       float* __restrict__ part)
{
    const int bh = blockIdx.x;
    const int b = bh / NH, h = bh % NH;
    const int chunk = blockIdx.y;
    const int NPER = NSEQ / KV_CHUNKS;   // 512
    const int n0 = chunk * NPER;

    __shared__ float Ks[16][64];
    __shared__ float Vs[16][64];

    const int tid = threadIdx.x;
    const int tk = (tid >> 4) * 4;
    const int tv = (tid & 15) * 4;

    float acc[4][4];
#pragma unroll
    for (int i = 0; i < 4; i++)
#pragma unroll
        for (int j = 0; j < 4; j++) acc[i][j] = 0.f;

    const int lr = tid >> 4;
    const int lc = (tid & 15) * 4;

    for (int n = n0; n < n0 + NPER; n += 16) {
        size_t basep = ((size_t)(b * NSEQ + n + lr)) * DMODEL + h * DK + lc;
        *(float4*)&Ks[lr][lc] = *(const float4*)(Kp + basep);
        *(float4*)&Vs[lr][lc] = *(const float4*)(Vp + basep);
        __syncthreads();
#pragma unroll
        for (int rr = 0; rr < 16; rr++) {
            float kr[4], vr[4];
#pragma unroll
            for (int i = 0; i < 4; i++) kr[i] = Ks[rr][tk + i];
#pragma unroll
            for (int j = 0; j < 4; j++) vr[j] = Vs[rr][tv + j];
#pragma unroll
            for (int i = 0; i < 4; i++)
#pragma unroll
                for (int j = 0; j < 4; j++)
                    acc[i][j] = fmaf(kr[i], vr[j], acc[i][j]);
        }
        __syncthreads();
    }

    float* out = part + ((size_t)chunk * BH + bh) * (DK * DV);
#pragma unroll
    for (int i = 0; i < 4; i++)
#pragma unroll
        for (int j = 0; j < 4; j++)
            out[(tk + i) * DV + tv + j] = acc[i][j];
}

// ---------------------------------------------------------------------------
__global__ __launch_bounds__(256)
void kv_reduce_norm_kernel(const float* __restrict__ part,
                           const float* __restrict__ gamma,
                           float* __restrict__ kvn)
{
    const int row = blockIdx.x * 8 + (threadIdx.x >> 5);
    const int lane = threadIdx.x & 31;
    const int bh = row >> 6;
    const int k  = row & 63;
    const int h  = bh % NH;

    float s0 = 0.f, s1 = 0.f;
#pragma unroll
    for (int c = 0; c < KV_CHUNKS; c++) {
        const float* p = part + ((size_t)c * BH + bh) * (DK * DV) + k * DV;
        s0 += p[lane];
        s1 += p[lane + 32];
    }
    float ss = s0 * s0 + s1 * s1;
#pragma unroll
    for (int off = 16; off > 0; off >>= 1)
        ss += __shfl_xor_sync(0xffffffffu, ss, off);
    float scale = gamma[h] * rsqrtf(ss);

    float* o = kvn + (size_t)bh * (DK * DV) + k * DV;
    o[lane]      = s0 * scale;
    o[lane + 32] = s1 * scale;
}

// ---------------------------------------------------------------------------
// mid = xnorm(q) @ kvn, written directly as fp16 hi/lo (feeds output GEMM)
// ---------------------------------------------------------------------------
__global__ __launch_bounds__(256)
void apply_kernel(const float* __restrict__ Qp, const float* __restrict__ kvn,
                  const float* __restrict__ gamma,
                  __half* __restrict__ mh, __half* __restrict__ ml)
{
    const int bh = blockIdx.x;
    const int b = bh / NH, h = bh % NH;

    __shared__ float Ks[64][65];
    __shared__ float qs[4][64];

    const int tid = threadIdx.x;
    for (int i = tid; i < DK * DV; i += 256)
        Ks[i >> 6][i & 63] = kvn[(size_t)bh * (DK * DV) + i];
    __syncthreads();

    const int g = tid >> 6;
    const int t = tid & 63;
    const float gh = gamma[h];
    const int n_base = blockIdx.y * 64;

    for (int it = 0; it < 16; it++) {
        int n = n_base + it * 4 + g;
        size_t qoff = ((size_t)(b * NSEQ + n)) * DMODEL + h * DK;
        qs[g][t] = Qp[qoff + t];
        __syncthreads();
        float acc = 0.f, qq = 0.f;
#pragma unroll
        for (int k = 0; k < DK; k++) {
            float qv = qs[g][k];
            qq  = fmaf(qv, qv, qq);
            acc = fmaf(qv, Ks[k][t], acc);
        }
        float val = acc * gh * rsqrtf(qq);
        __half hv = __float2half(val);
        mh[qoff + t] = hv;
        ml[qoff + t] = __float2half(val - __half2float(hv));
        __syncthreads();
    }
}

// ---------------------------------------------------------------------------
extern "C" void kernel_launch(void* const* d_in, const int* in_sizes, int n_in,
                              void* d_out, int out_size)
{
    const float* queries = (const float*)d_in[0];
    const float* keys    = (const float*)d_in[1];
    const float* values  = (const float*)d_in[2];
    const float* Wq = (const float*)d_in[3];
    const float* bq = (const float*)d_in[4];
    const float* Wk = (const float*)d_in[5];
    const float* bk = (const float*)d_in[6];
    const float* Wv = (const float*)d_in[7];
    const float* bv = (const float*)d_in[8];
    const float* Wo = (const float*)d_in[9];
    const float* bo = (const float*)d_in[10];
    const float* gamma = (const float*)d_in[11];
    float* out = (float*)d_out;

    float *q, *k, *v, *kvpart, *kvn;
    __half *ah, *al, *wh;
    cudaGetSymbolAddress((void**)&q,      g_q);
    cudaGetSymbolAddress((void**)&k,      g_k);
    cudaGetSymbolAddress((void**)&v,      g_v);
    cudaGetSymbolAddress((void**)&kvpart, g_kvpart);
    cudaGetSymbolAddress((void**)&kvn,    g_kvn);
    cudaGetSymbolAddress((void**)&ah,     g_ah);
    cudaGetSymbolAddress((void**)&al,     g_al);
    cudaGetSymbolAddress((void**)&wh,     g_wh);

    cudaFuncSetAttribute(gemm_fp16x2, cudaFuncAttributeMaxDynamicSharedMemorySize, DSMEM_SZ);

    const int ACT_N4 = MROWS * DMODEL / 4;    // 4M float4
    const int W_N4   = DMODEL * DMODEL / 4;   // 256K float4
    dim3 gemm_grid(DMODEL / GN, MROWS / GM);  // (8, 128)

    // Q projection
    split_act_kernel<<<ACT_N4 / 256, 256>>>((const float4*)queries, ah, al, ACT_N4);
    split_w_kernel<<<W_N4 / 256, 256>>>((const float4*)Wq, wh, W_N4);
    gemm_fp16x2<<<gemm_grid, 256, DSMEM_SZ>>>(ah, al, wh, bq, q);

    // K projection
    split_act_kernel<<<ACT_N4 / 256, 256>>>((const float4*)keys, ah, al, ACT_N4);
    split_w_kernel<<<W_N4 / 256, 256>>>((const float4*)Wk, wh, W_N4);
    gemm_fp16x2<<<gemm_grid, 256, DSMEM_SZ>>>(ah, al, wh, bk, k);

    // V projection
    split_act_kernel<<<ACT_N4 / 256, 256>>>((const float4*)values, ah, al, ACT_N4);
    split_w_kernel<<<W_N4 / 256, 256>>>((const float4*)Wv, wh, W_N4);
    gemm_fp16x2<<<gemm_grid, 256, DSMEM_SZ>>>(ah, al, wh, bv, v);

    // kv = K^T V per head; normalize; apply to normalized q (writes fp16 hi/lo mid)
    kv_partial_kernel<<<dim3(BH, KV_CHUNKS), 256>>>(k, v, kvpart);
    kv_reduce_norm_kernel<<<dim3(BH * DK / 8), 256>>>(kvpart, gamma, kvn);
    apply_kernel<<<dim3(BH, NSEQ / 64), 256>>>(q, kvn, gamma, ah, al);

    // output projection (mid already split in apply_kernel)
    split_w_kernel<<<W_N4 / 256, 256>>>((const float4*)Wo, wh, W_N4);
    gemm_fp16x2<<<gemm_grid, 256, DSMEM_SZ>>>(ah, al, wh, bo, out);
}

// round 16
// speedup vs baseline: 3.3052x; 1.0442x over previous
#include <cuda_runtime.h>
#include <cuda_bf16.h>
#include <cuda_fp16.h>
#include <cstdint>

// Problem constants
#define BATCH   4
#define NSEQ    4096
#define DMODEL  1024
#define NH      16
#define DK      64
#define DV      64
#define MROWS   (BATCH * NSEQ)      // 16384
#define BH      (BATCH * NH)        // 64
#define KV_CHUNKS 8

#define WSCALE   256.0f
#define INV_WSCALE (1.0f / 256.0f)

// Scratch (device globals: allocation-free rule)
__device__ float g_q[MROWS * DMODEL];
__device__ float g_k[MROWS * DMODEL];
__device__ float g_v[MROWS * DMODEL];
__device__ float g_kvpart[KV_CHUNKS * BH * DK * DV];
__device__ float g_kvn[BH * DK * DV];
__device__ __half g_ah[MROWS * DMODEL];   // activation hi
__device__ __half g_al[MROWS * DMODEL];   // activation lo
__device__ __half g_wh[DMODEL * DMODEL];  // weight (x256) fp16

// ---------------------------------------------------------------------------
// helpers (baseline ISA only: cp.async, ldmatrix, mma.sync — all sm_80+)
// ---------------------------------------------------------------------------
__device__ __forceinline__ uint32_t smem_u32(const void* p) {
    uint32_t a;
    asm("{ .reg .u64 t; cvta.to.shared.u64 t, %1; cvt.u32.u64 %0, t; }"
        : "=r"(a) : "l"(p));
    return a;
}
__device__ __forceinline__ void cp16(uint32_t s, const void* g) {
    asm volatile("cp.async.cg.shared.global [%0], [%1], 16;" :: "r"(s), "l"(g));
}
__device__ __forceinline__ void cp_commit() {
    asm volatile("cp.async.commit_group;" ::: "memory");
}
__device__ __forceinline__ void cp_wait_allbut2() {
    asm volatile("cp.async.wait_group 2;" ::: "memory");
}
// SW64 swizzle for 64-byte rows (8 rows x 64B atom); conflict-free for
// 16B-granular ldmatrix reads and cp.async 16B stores.
__device__ __forceinline__ uint32_t swz64(uint32_t off) {
    return off ^ ((off >> 3) & 0x30);
}
__device__ __forceinline__ void ldsm_x4(uint32_t (&r)[4], uint32_t addr) {
    asm volatile("ldmatrix.sync.aligned.m8n8.x4.shared.b16 {%0,%1,%2,%3}, [%4];"
                 : "=r"(r[0]), "=r"(r[1]), "=r"(r[2]), "=r"(r[3]) : "r"(addr));
}
__device__ __forceinline__ void mma16816(float* c, const uint32_t* a, const uint32_t* b) {
    asm volatile("mma.sync.aligned.m16n8k16.row.col.f32.f16.f16.f32 "
                 "{%0,%1,%2,%3}, {%4,%5,%6,%7}, {%8,%9}, {%0,%1,%2,%3};"
                 : "+f"(c[0]), "+f"(c[1]), "+f"(c[2]), "+f"(c[3])
                 : "r"(a[0]), "r"(a[1]), "r"(a[2]), "r"(a[3]), "r"(b[0]), "r"(b[1]));
}

// ---------------------------------------------------------------------------
// fp32 -> fp16 hi/lo split for activations (vectorized by 4)
// ---------------------------------------------------------------------------
__global__ __launch_bounds__(256)
void split_act_kernel(const float4* __restrict__ x, __half* __restrict__ hi,
                      __half* __restrict__ lo, int n4)
{
    int i = blockIdx.x * 256 + threadIdx.x;
    if (i >= n4) return;
    float4 v = x[i];
    __half h0 = __float2half(v.x), h1 = __float2half(v.y);
    __half h2 = __float2half(v.z), h3 = __float2half(v.w);
    __half l0 = __float2half(v.x - __half2float(h0));
    __half l1 = __float2half(v.y - __half2float(h1));
    __half l2 = __float2half(v.z - __half2float(h2));
    __half l3 = __float2half(v.w - __half2float(h3));
    size_t o = (size_t)i * 4;
    *(__half2*)(hi + o)     = __halves2half2(h0, h1);
    *(__half2*)(hi + o + 2) = __halves2half2(h2, h3);
    *(__half2*)(lo + o)     = __halves2half2(l0, l1);
    *(__half2*)(lo + o + 2) = __halves2half2(l2, l3);
}

// fp32 -> fp16 weight convert with x256 scale (keeps values in normal range)
__global__ __launch_bounds__(256)
void split_w_kernel(const float4* __restrict__ x, __half* __restrict__ hi, int n4)
{
    int i = blockIdx.x * 256 + threadIdx.x;
    if (i >= n4) return;
    float4 v = x[i];
    size_t o = (size_t)i * 4;
    *(__half2*)(hi + o)     = __halves2half2(__float2half(v.x * WSCALE), __float2half(v.y * WSCALE));
    *(__half2*)(hi + o + 2) = __halves2half2(__float2half(v.z * WSCALE), __float2half(v.w * WSCALE));
}

// ---------------------------------------------------------------------------
// HMMA fp16x2 GEMM: C[M,1024] = A[M,1024] x B[1024,1024]^T * (1/256) + bias
// A as (hi,lo) fp16 pair, B as fp16 (x256). CTA tile 128x128, BK=32,
// 4-buffer / 3-in-flight cp.async pipeline, 8 warps (4M x 2N), warp 32x64.
// 96KB smem/CTA -> 2 CTAs/SM for bubble overlap.
// ---------------------------------------------------------------------------
#define GM 128
#define GN 128
#define GK 32
#define NSTAGE 4
#define TILE_B   8192                  // 128 rows x 64 bytes (32 fp16)
#define STAGE_B  (3 * TILE_B)          // Ah, Al, Bh = 24KB
#define KITERS   (DMODEL / GK)         // 32
#define DSMEM_SZ (NSTAGE * STAGE_B + 1024)

__device__ __forceinline__ void load_stage(uint32_t base, int s, int tid,
    const __half* __restrict__ Ah, const __half* __restrict__ Al,
    const __half* __restrict__ Bh, int bm, int bn)
{
    uint32_t sb = base + (s % NSTAGE) * STAGE_B;
    const __half* srcs[3] = {
        Ah + (size_t)bm * DMODEL + s * GK,
        Al + (size_t)bm * DMODEL + s * GK,
        Bh + (size_t)bn * DMODEL + s * GK };
#pragma unroll
    for (int t = 0; t < 3; t++) {
        const __half* P = srcs[t];
        uint32_t tb = sb + t * TILE_B;
#pragma unroll
        for (int i = 0; i < 2; i++) {
            int chunk = tid + i * 256;       // 0..511 16B chunks
            int r = chunk >> 2;              // row 0..127
            int c = chunk & 3;               // 16B chunk 0..3
            cp16(tb + swz64(r * 64 + c * 16), P + (size_t)r * DMODEL + c * 8);
        }
    }
}

__global__ __launch_bounds__(256, 2)
void gemm_fp16x2(const __half* __restrict__ Ah, const __half* __restrict__ Al,
                 const __half* __restrict__ Bh,
                 const float* __restrict__ bias, float* __restrict__ C)
{
    extern __shared__ char dsm[];
    const int tid = threadIdx.x;
    const int wid = tid >> 5;
    const int lane = tid & 31;
    const int wm = wid & 3;          // warp row 0..3  (32 rows each)
    const int wn = wid >> 2;         // warp col 0..1  (64 cols each)
    const int bm = blockIdx.y * GM;
    const int bn = blockIdx.x * GN;

    uint32_t base = (smem_u32(dsm) + 1023) & ~1023u;

    // ldmatrix lane address components
    const int a_r  = (lane & 15);
    const int a_kh = ((lane >> 4) & 1) * 16;
    const int b_g  = lane >> 3;
    const int b_r  = (lane & 7) + ((b_g >> 1) << 3);
    const int b_kh = (b_g & 1) * 16;

    float acc[2][8][4];
#pragma unroll
    for (int mt = 0; mt < 2; mt++)
#pragma unroll
        for (int nt = 0; nt < 8; nt++)
#pragma unroll
            for (int j = 0; j < 4; j++) acc[mt][nt][j] = 0.f;

    // prologue: fill 3 of 4 buffers
    load_stage(base, 0, tid, Ah, Al, Bh, bm, bn); cp_commit();
    load_stage(base, 1, tid, Ah, Al, Bh, bm, bn); cp_commit();
    load_stage(base, 2, tid, Ah, Al, Bh, bm, bn); cp_commit();

    for (int s = 0; s < KITERS; s++) {
        cp_wait_allbut2();               // stage s resident
        __syncthreads();                 // also orders reuse of buffer (s+3)%4

        // issue next load BEFORE compute (targets buffer (s+3)%4 != s%4)
        if (s + 3 < KITERS)
            load_stage(base, s + 3, tid, Ah, Al, Bh, bm, bn);
        cp_commit();                     // uniform group count

        uint32_t sb  = base + (s % NSTAGE) * STAGE_B;
        uint32_t Ahb = sb, Alb = sb + TILE_B, Bhb = sb + 2 * TILE_B;

#pragma unroll
        for (int ks = 0; ks < 2; ks++) {     // 2 x k16 per stage
            const int kb = ks * 32;
            uint32_t ah[2][4], al[2][4];
#pragma unroll
            for (int mt = 0; mt < 2; mt++) {
                uint32_t off = swz64((wm * 32 + mt * 16 + a_r) * 64 + kb + a_kh);
                ldsm_x4(ah[mt], Ahb + off);
                ldsm_x4(al[mt], Alb + off);
            }
#pragma unroll
            for (int nt = 0; nt < 4; nt++) { // pairs of n8 groups
                uint32_t boff = swz64((wn * 64 + nt * 16 + b_r) * 64 + kb + b_kh);
                uint32_t bh[4];
                ldsm_x4(bh, Bhb + boff);
#pragma unroll
                for (int mt = 0; mt < 2; mt++) {
                    mma16816(acc[mt][nt * 2],     ah[mt], bh);
                    mma16816(acc[mt][nt * 2],     al[mt], bh);
                    mma16816(acc[mt][nt * 2 + 1], ah[mt], bh + 2);
                    mma16816(acc[mt][nt * 2 + 1], al[mt], bh + 2);
                }
            }
        }
    }

    // epilogue: c0,c1 -> row g; c2,c3 -> row g+8; scale by 1/256, add bias
    const int g = lane >> 2, t = lane & 3;
#pragma unroll
    for (int mt = 0; mt < 2; mt++) {
        const int row0 = bm + wm * 32 + mt * 16 + g;
#pragma unroll
        for (int nt = 0; nt < 8; nt++) {
            const int col = bn + wn * 64 + nt * 8 + t * 2;
            const float b0 = bias[col], b1 = bias[col + 1];
            float2 o0 = make_float2(fmaf(acc[mt][nt][0], INV_WSCALE, b0),
                                    fmaf(acc[mt][nt][1], INV_WSCALE, b1));
            float2 o1 = make_float2(fmaf(acc[mt][nt][2], INV_WSCALE, b0),
                                    fmaf(acc[mt][nt][3], INV_WSCALE, b1));
            *(float2*)(C + (size_t)row0 * DMODEL + col)       = o0;
            *(float2*)(C + (size_t)(row0 + 8) * DMODEL + col) = o1;
        }
    }
}

// ---------------------------------------------------------------------------
// kv partial: part[chunk][bh][k][v] = sum over n in chunk of K[b,n,h,k]*V[b,n,h,v]
// ---------------------------------------------------------------------------
__global__ __launch_bounds__(256)
void kv_partial_kernel(const float* __restrict__ Kp, const float* __restrict__ Vp,
                       float* __restrict__ part)
{
    const int bh = blockIdx.x;
    const int b = bh / NH, h = bh % NH;
    const int chunk = blockIdx.y;
    const int NPER = NSEQ / KV_CHUNKS;   // 512
    const int n0 = chunk * NPER;

    __shared__ float Ks[16][64];
    __shared__ float Vs[16][64];

    const int tid = threadIdx.x;
    const int tk = (tid >> 4) * 4;
    const int tv = (tid & 15) * 4;

    float acc[4][4];
#pragma unroll
    for (int i = 0; i < 4; i++)
#pragma unroll
        for (int j = 0; j < 4; j++) acc[i][j] = 0.f;

    const int lr = tid >> 4;
    const int lc = (tid & 15) * 4;

    for (int n = n0; n < n0 + NPER; n += 16) {
        size_t basep = ((size_t)(b * NSEQ + n + lr)) * DMODEL + h * DK + lc;
        *(float4*)&Ks[lr][lc] = *(const float4*)(Kp + basep);
        *(float4*)&Vs[lr][lc] = *(const float4*)(Vp + basep);
        __syncthreads();
#pragma unroll
        for (int rr = 0; rr < 16; rr++) {
            float kr[4], vr[4];
#pragma unroll
            for (int i = 0; i < 4; i++) kr[i] = Ks[rr][tk + i];
#pragma unroll
            for (int j = 0; j < 4; j++) vr[j] = Vs[rr][tv + j];
#pragma unroll
            for (int i = 0; i < 4; i++)
#pragma unroll
                for (int j = 0; j < 4; j++)
                    acc[i][j] = fmaf(kr[i], vr[j], acc[i][j]);
        }
        __syncthreads();
    }

    float* out = part + ((size_t)chunk * BH + bh) * (DK * DV);
#pragma unroll
    for (int i = 0; i < 4; i++)
#pragma unroll
        for (int j = 0; j < 4; j++)
            out[(tk + i) * DV + tv + j] = acc[i][j];
}

// ---------------------------------------------------------------------------
__global__ __launch_bounds__(256)
void kv_reduce_norm_kernel(const float* __restrict__ part,
                           const float* __restrict__ gamma,
                           float* __restrict__ kvn)
{
    const int row = blockIdx.x * 8 + (threadIdx.x >> 5);
    const int lane = threadIdx.x & 31;
    const int bh = row >> 6;
    const int k  = row & 63;
    const int h  = bh % NH;

    float s0 = 0.f, s1 = 0.f;
#pragma unroll
    for (int c = 0; c < KV_CHUNKS; c++) {
        const float* p = part + ((size_t)c * BH + bh) * (DK * DV) + k * DV;
        s0 += p[lane];
        s1 += p[lane + 32];
    }
    float ss = s0 * s0 + s1 * s1;
#pragma unroll
    for (int off = 16; off > 0; off >>= 1)
        ss += __shfl_xor_sync(0xffffffffu, ss, off);
    float scale = gamma[h] * rsqrtf(ss);

    float* o = kvn + (size_t)bh * (DK * DV) + k * DV;
    o[lane]      = s0 * scale;
    o[lane + 32] = s1 * scale;
}

// ---------------------------------------------------------------------------
// mid = xnorm(q) @ kvn, written directly as fp16 hi/lo (feeds output GEMM)
// ---------------------------------------------------------------------------
__global__ __launch_bounds__(256)
void apply_kernel(const float* __restrict__ Qp, const float* __restrict__ kvn,
                  const float* __restrict__ gamma,
                  __half* __restrict__ mh, __half* __restrict__ ml)
{
    const int bh = blockIdx.x;
    const int b = bh / NH, h = bh % NH;

    __shared__ float Ks[64][65];
    __shared__ float qs[4][64];

    const int tid = threadIdx.x;
    for (int i = tid; i < DK * DV; i += 256)
        Ks[i >> 6][i & 63] = kvn[(size_t)bh * (DK * DV) + i];
    __syncthreads();

    const int g = tid >> 6;
    const int t = tid & 63;
    const float gh = gamma[h];
    const int n_base = blockIdx.y * 64;

    for (int it = 0; it < 16; it++) {
        int n = n_base + it * 4 + g;
        size_t qoff = ((size_t)(b * NSEQ + n)) * DMODEL + h * DK;
        qs[g][t] = Qp[qoff + t];
        __syncthreads();
        float acc = 0.f, qq = 0.f;
#pragma unroll
        for (int k = 0; k < DK; k++) {
            float qv = qs[g][k];
            qq  = fmaf(qv, qv, qq);
            acc = fmaf(qv, Ks[k][t], acc);
        }
        float val = acc * gh * rsqrtf(qq);
        __half hv = __float2half(val);
        mh[qoff + t] = hv;
        ml[qoff + t] = __float2half(val - __half2float(hv));
        __syncthreads();
    }
}

// ---------------------------------------------------------------------------
extern "C" void kernel_launch(void* const* d_in, const int* in_sizes, int n_in,
                              void* d_out, int out_size)
{
    const float* queries = (const float*)d_in[0];
    const float* keys    = (const float*)d_in[1];
    const float* values  = (const float*)d_in[2];
    const float* Wq = (const float*)d_in[3];
    const float* bq = (const float*)d_in[4];
    const float* Wk = (const float*)d_in[5];
    const float* bk = (const float*)d_in[6];
    const float* Wv = (const float*)d_in[7];
    const float* bv = (const float*)d_in[8];
    const float* Wo = (const float*)d_in[9];
    const float* bo = (const float*)d_in[10];
    const float* gamma = (const float*)d_in[11];
    float* out = (float*)d_out;

    float *q, *k, *v, *kvpart, *kvn;
    __half *ah, *al, *wh;
    cudaGetSymbolAddress((void**)&q,      g_q);
    cudaGetSymbolAddress((void**)&k,      g_k);
    cudaGetSymbolAddress((void**)&v,      g_v);
    cudaGetSymbolAddress((void**)&kvpart, g_kvpart);
    cudaGetSymbolAddress((void**)&kvn,    g_kvn);
    cudaGetSymbolAddress((void**)&ah,     g_ah);
    cudaGetSymbolAddress((void**)&al,     g_al);
    cudaGetSymbolAddress((void**)&wh,     g_wh);

    cudaFuncSetAttribute(gemm_fp16x2, cudaFuncAttributeMaxDynamicSharedMemorySize, DSMEM_SZ);

    const int ACT_N4 = MROWS * DMODEL / 4;    // 4M float4
    const int W_N4   = DMODEL * DMODEL / 4;   // 256K float4
    dim3 gemm_grid(DMODEL / GN, MROWS / GM);  // (8, 128)

    // Q projection
    split_act_kernel<<<ACT_N4 / 256, 256>>>((const float4*)queries, ah, al, ACT_N4);
    split_w_kernel<<<W_N4 / 256, 256>>>((const float4*)Wq, wh, W_N4);
    gemm_fp16x2<<<gemm_grid, 256, DSMEM_SZ>>>(ah, al, wh, bq, q);

    // K projection
    split_act_kernel<<<ACT_N4 / 256, 256>>>((const float4*)keys, ah, al, ACT_N4);
    split_w_kernel<<<W_N4 / 256, 256>>>((const float4*)Wk, wh, W_N4);
    gemm_fp16x2<<<gemm_grid, 256, DSMEM_SZ>>>(ah, al, wh, bk, k);

    // V projection
    split_act_kernel<<<ACT_N4 / 256, 256>>>((const float4*)values, ah, al, ACT_N4);
    split_w_kernel<<<W_N4 / 256, 256>>>((const float4*)Wv, wh, W_N4);
    gemm_fp16x2<<<gemm_grid, 256, DSMEM_SZ>>>(ah, al, wh, bv, v);

    // kv = K^T V per head; normalize; apply to normalized q (writes fp16 hi/lo mid)
    kv_partial_kernel<<<dim3(BH, KV_CHUNKS), 256>>>(k, v, kvpart);
    kv_reduce_norm_kernel<<<dim3(BH * DK / 8), 256>>>(kvpart, gamma, kvn);
    apply_kernel<<<dim3(BH, NSEQ / 64), 256>>>(q, kvn, gamma, ah, al);

    // output projection (mid already split in apply_kernel)
    split_w_kernel<<<W_N4 / 256, 256>>>((const float4*)Wo, wh, W_N4);
    gemm_fp16x2<<<gemm_grid, 256, DSMEM_SZ>>>(ah, al, wh, bo, out);
}